// round 1
// baseline (speedup 1.0000x reference)
#include <cuda_runtime.h>
#include <cuda_bf16.h>
#include <math.h>

#define NN 50000
#define EE 800000
#define DINN 64
#define DOUTN 64
#define KKER 8
#define CTOT 576   // 512 (W_g) + 64 (W_root)

// ---------------- scratch (static device globals; no allocation) ------------
__device__ float g_xt[(size_t)NN * 512];     // x @ W_g, [N, K*DOUT] = 102.4 MB
__device__ float g_root[(size_t)NN * 64];    // x @ W_root                12.8 MB
__device__ float g_agg[(size_t)NN * 64];     // scatter target             12.8 MB
__device__ float g_cnt[NN];
__device__ float g_sums[128];                // [0:64) sum, [64:128) sumsq
__device__ int   g_is64;

// ---------------- K_detect: sniff edge_idx dtype (int64 vs int32) ----------
__global__ void k_detect(const int* __restrict__ eidx_raw) {
    if (threadIdx.x == 0 && blockIdx.x == 0) {
        // If int64 little-endian with values < 2^31, every odd 32-bit word is 0.
        int acc = 0;
        for (int i = 0; i < 2048; i++) acc |= eidx_raw[2 * i + 1];
        g_is64 = (acc == 0) ? 1 : 0;
    }
}

// ---------------- K_zero ----------------------------------------------------
__global__ void k_zero() {
    long i = (long)blockIdx.x * blockDim.x + threadIdx.x;
    const long nagg = (long)NN * 64;
    if (i < nagg) g_agg[i] = 0.0f;
    else if (i < nagg + NN) g_cnt[i - nagg] = 0.0f;
    else if (i < nagg + NN + 128) g_sums[i - nagg - NN] = 0.0f;
}

// ---------------- K_gemm: C[N,576] = x[N,64] @ [W_g | W_root] ---------------
__global__ __launch_bounds__(256) void k_gemm(
    const float* __restrict__ x, const float* __restrict__ Wg,
    const float* __restrict__ Wr)
{
    __shared__ float As[64][65];
    __shared__ float Bs[64][65];

    const int row0 = blockIdx.x * 64;
    const int col0 = blockIdx.y * 64;
    const int tid  = threadIdx.x;

    // load A tile (64 rows x 64 k)
    #pragma unroll
    for (int i = tid; i < 64 * 64; i += 256) {
        int r = i >> 6, c = i & 63;
        int gr = row0 + r;
        As[r][c] = (gr < NN) ? x[(size_t)gr * 64 + c] : 0.0f;
    }
    // load B tile (64 k x 64 cols), selecting W_g or W_root by column
    #pragma unroll
    for (int i = tid; i < 64 * 64; i += 256) {
        int k = i >> 6, c = i & 63;
        int gc = col0 + c;
        Bs[k][c] = (gc < 512) ? Wg[k * 512 + gc] : Wr[k * 64 + (gc - 512)];
    }
    __syncthreads();

    const int tr = (tid >> 4) << 2;   // 0..60
    const int tc = (tid & 15) << 2;   // 0..60

    float acc[4][4] = {};
    #pragma unroll
    for (int k = 0; k < 64; k++) {
        float a[4], b[4];
        #pragma unroll
        for (int i = 0; i < 4; i++) a[i] = As[tr + i][k];
        #pragma unroll
        for (int j = 0; j < 4; j++) b[j] = Bs[k][tc + j];
        #pragma unroll
        for (int i = 0; i < 4; i++)
            #pragma unroll
            for (int j = 0; j < 4; j++)
                acc[i][j] = fmaf(a[i], b[j], acc[i][j]);
    }

    #pragma unroll
    for (int i = 0; i < 4; i++) {
        int gr = row0 + tr + i;
        if (gr >= NN) continue;
        #pragma unroll
        for (int j = 0; j < 4; j++) {
            int gc = col0 + tc + j;
            if (gc < 512) g_xt[(size_t)gr * 512 + gc] = acc[i][j];
            else          g_root[(size_t)gr * 64 + (gc - 512)] = acc[i][j];
        }
    }
}

// ---------------- K_edge: gather / weight / scatter --------------------------
__global__ __launch_bounds__(256) void k_edge(
    const void* __restrict__ eidx,
    const float* __restrict__ eattr,
    const float* __restrict__ mu,
    const float* __restrict__ sigma)
{
    const int lane  = threadIdx.x & 31;
    const int warp  = ((int)blockIdx.x * (int)blockDim.x + (int)threadIdx.x) >> 5;
    const int nwarp = ((int)gridDim.x * (int)blockDim.x) >> 5;
    const int is64  = g_is64;

    // lanes 0..7: per-kernel Gaussian params
    float m0 = 0.f, m1 = 0.f, m2 = 0.f, iv0 = 0.f, iv1 = 0.f, iv2 = 0.f;
    if (lane < KKER) {
        m0 = mu[lane * 3 + 0]; m1 = mu[lane * 3 + 1]; m2 = mu[lane * 3 + 2];
        float s0 = sigma[lane * 3 + 0], s1 = sigma[lane * 3 + 1], s2 = sigma[lane * 3 + 2];
        iv0 = -0.5f / (1e-15f + s0 * s0);
        iv1 = -0.5f / (1e-15f + s1 * s1);
        iv2 = -0.5f / (1e-15f + s2 * s2);
    }

    const long long* e64 = (const long long*)eidx;
    const int*       e32 = (const int*)eidx;

    for (int e = warp; e < EE; e += nwarp) {
        long long src, dst;
        if (is64) { src = e64[e]; dst = e64[EE + e]; }
        else      { src = e32[e]; dst = e32[EE + e]; }

        float a0 = eattr[(size_t)e * 3 + 0];
        float a1 = eattr[(size_t)e * 3 + 1];
        float a2 = eattr[(size_t)e * 3 + 2];

        float gk = 0.0f;
        if (lane < KKER) {
            float d0 = a0 - m0, d1 = a1 - m1, d2 = a2 - m2;
            gk = __expf(d0 * d0 * iv0 + d1 * d1 * iv1 + d2 * d2 * iv2);
        }

        const float* xr = g_xt + (size_t)src * 512;
        float v0[8], v1[8];
        #pragma unroll
        for (int k = 0; k < 8; k++) {
            v0[k] = xr[k * 64 + lane];
            v1[k] = xr[k * 64 + 32 + lane];
        }
        float acc0 = 0.0f, acc1 = 0.0f;
        #pragma unroll
        for (int k = 0; k < 8; k++) {
            float g = __shfl_sync(0xffffffffu, gk, k);
            acc0 = fmaf(g, v0[k], acc0);
            acc1 = fmaf(g, v1[k], acc1);
        }

        atomicAdd(&g_agg[(size_t)dst * 64 + lane], acc0);
        atomicAdd(&g_agg[(size_t)dst * 64 + 32 + lane], acc1);
        if (lane == 0) atomicAdd(&g_cnt[dst], 1.0f);
    }
}

// ---------------- K_combine: pre-BN values + channel sums -------------------
__global__ __launch_bounds__(256) void k_combine(
    const float* __restrict__ bias, float* __restrict__ out)
{
    const int c = threadIdx.x & 63;
    const int w = threadIdx.x >> 6;   // 0..3
    const float b = bias[c];

    float s = 0.0f, ss = 0.0f;
    for (int n = blockIdx.x * 4 + w; n < NN; n += gridDim.x * 4) {
        float cnt = g_cnt[n];
        float inv = 1.0f / fmaxf(cnt, 1.0f);
        float v = g_agg[(size_t)n * 64 + c] * inv + g_root[(size_t)n * 64 + c] + b;
        out[(size_t)n * 64 + c] = v;
        s += v; ss += v * v;
    }

    __shared__ float shs[4][64];
    __shared__ float shq[4][64];
    shs[w][c] = s; shq[w][c] = ss;
    __syncthreads();
    if (threadIdx.x < 64) {
        float S  = shs[0][c] + shs[1][c] + shs[2][c] + shs[3][c];
        float SS = shq[0][c] + shq[1][c] + shq[2][c] + shq[3][c];
        atomicAdd(&g_sums[c], S);
        atomicAdd(&g_sums[64 + c], SS);
    }
}

// ---------------- K_norm: batchnorm + leaky relu -----------------------------
__global__ __launch_bounds__(256) void k_norm(
    const float* __restrict__ gamma, const float* __restrict__ beta,
    float* __restrict__ out)
{
    long i = (long)blockIdx.x * blockDim.x + threadIdx.x;
    if (i >= (long)NN * 64) return;
    int c = (int)(i & 63);
    const float invN = 1.0f / (float)NN;
    float mean = g_sums[c] * invN;
    float var  = g_sums[64 + c] * invN - mean * mean;
    float v = (out[i] - mean) * rsqrtf(var + 1e-5f) * gamma[c] + beta[c];
    out[i] = (v > 0.0f) ? v : 0.01f * v;
}

// ---------------- launcher ---------------------------------------------------
extern "C" void kernel_launch(void* const* d_in, const int* in_sizes, int n_in,
                              void* d_out, int out_size)
{
    const float* x      = (const float*)d_in[0];
    const void*  eidx   = d_in[1];
    const float* eattr  = (const float*)d_in[2];
    const float* Wg     = (const float*)d_in[3];
    const float* mu     = (const float*)d_in[4];
    const float* sigma  = (const float*)d_in[5];
    const float* Wr     = (const float*)d_in[6];
    const float* bias   = (const float*)d_in[7];
    const float* gamma  = (const float*)d_in[8];
    const float* beta   = (const float*)d_in[9];
    float* out = (float*)d_out;

    // zero scratch
    {
        long total = (long)NN * 64 + NN + 128;
        int blocks = (int)((total + 255) / 256);
        k_zero<<<blocks, 256>>>();
    }
    // dtype sniff for edge_idx
    k_detect<<<1, 32>>>((const int*)eidx);
    // GEMM: x @ [W_g | W_root]
    {
        dim3 grid((NN + 63) / 64, CTOT / 64);
        k_gemm<<<grid, 256>>>(x, Wg, Wr);
    }
    // edge gather/scatter
    k_edge<<<2368, 256>>>(eidx, eattr, mu, sigma);
    // combine + batch stats
    k_combine<<<512, 256>>>(bias, out);
    // normalize + activation
    {
        int blocks = (int)(((long)NN * 64 + 255) / 256);
        k_norm<<<blocks, 256>>>(gamma, beta, out);
    }
}

// round 3
// speedup vs baseline: 1.2278x; 1.2278x over previous
#include <cuda_runtime.h>
#include <cuda_fp16.h>
#include <math.h>

#define NN 50000
#define EE 800000
#define KKER 8

// ---------------- scratch (static device globals; no allocation) ------------
__device__ __half2 g_xt_h[(size_t)NN * 256];  // packed x@W_g: [N][K=8][32] half2 = 51.2 MB
__device__ float   g_root[(size_t)NN * 64];   // x @ W_root   12.8 MB
__device__ float   g_agg[(size_t)NN * 64];    // scatter target 12.8 MB
__device__ float   g_cnt[NN];
__device__ float   g_sums[128];               // [0:64) sum, [64:128) sumsq
__device__ int     g_is64;

// ---------------- K_detect: sniff edge_idx dtype (int64 vs int32) ----------
__global__ void k_detect(const int* __restrict__ eidx_raw) {
    if (threadIdx.x == 0 && blockIdx.x == 0) {
        int acc = 0;
        for (int i = 0; i < 2048; i++) acc |= eidx_raw[2 * i + 1];
        g_is64 = (acc == 0) ? 1 : 0;
    }
}

// ---------------- K_zero ----------------------------------------------------
__global__ void k_zero() {
    long i = (long)blockIdx.x * blockDim.x + threadIdx.x;
    const long nagg = (long)NN * 64;
    if (i < nagg) g_agg[i] = 0.0f;
    else if (i < nagg + NN) g_cnt[i - nagg] = 0.0f;
    else if (i < nagg + NN + 128) g_sums[i - nagg - NN] = 0.0f;
}

// ---------------- K_gemm: C[N,576] = x[N,64] @ [W_g | W_root] ---------------
// blockIdx.y in [0,8): one GMM kernel k each, output packed half2.
// blockIdx.y == 8: root weight, output fp32.
// Shared tiles padded to 68 floats/row: stride 272 B (16B-multiple) so the
// float4 loads below are always aligned.
__global__ __launch_bounds__(256) void k_gemm(
    const float* __restrict__ x, const float* __restrict__ Wg,
    const float* __restrict__ Wr)
{
    __shared__ float As[64][68];   // A stored k-major: As[k][row]
    __shared__ float Bs[64][68];   // Bs[k][col]

    const int row0 = blockIdx.x * 64;
    const int kblk = blockIdx.y;      // 0..8
    const int col0 = kblk * 64;
    const int tid  = threadIdx.x;

    // load A tile transposed: As[c][r] = x[row0+r][c]
    #pragma unroll
    for (int i = tid; i < 64 * 64; i += 256) {
        int r = i >> 6, c = i & 63;
        int gr = row0 + r;
        As[c][r] = (gr < NN) ? x[(size_t)gr * 64 + c] : 0.0f;
    }
    // load B tile: Bs[k][c]
    #pragma unroll
    for (int i = tid; i < 64 * 64; i += 256) {
        int k = i >> 6, c = i & 63;
        int gc = col0 + c;
        Bs[k][c] = (gc < 512) ? Wg[k * 512 + gc] : Wr[k * 64 + (gc - 512)];
    }
    __syncthreads();

    const int tr = (tid >> 4) << 2;   // 0..60, multiple of 4
    const int tc = (tid & 15) << 2;   // 0..60, multiple of 4

    float acc[4][4] = {};
    #pragma unroll
    for (int k = 0; k < 64; k++) {
        float4 a = *(const float4*)&As[k][tr];
        float4 b = *(const float4*)&Bs[k][tc];
        float av[4] = {a.x, a.y, a.z, a.w};
        float bv[4] = {b.x, b.y, b.z, b.w};
        #pragma unroll
        for (int i = 0; i < 4; i++)
            #pragma unroll
            for (int j = 0; j < 4; j++)
                acc[i][j] = fmaf(av[i], bv[j], acc[i][j]);
    }

    if (kblk < 8) {
        // stage fp32 tile to shared, then pack (c, c+32) into half2
        __syncthreads();
        #pragma unroll
        for (int i = 0; i < 4; i++)
            #pragma unroll
            for (int j = 0; j < 4; j++)
                As[tr + i][tc + j] = acc[i][j];
        __syncthreads();
        #pragma unroll
        for (int i = tid; i < 64 * 32; i += 256) {
            int r = i >> 5, c = i & 31;
            int gr = row0 + r;
            if (gr < NN) {
                __half2 h = __floats2half2_rn(As[r][c], As[r][c + 32]);
                g_xt_h[(size_t)gr * 256 + kblk * 32 + c] = h;
            }
        }
    } else {
        #pragma unroll
        for (int i = 0; i < 4; i++) {
            int gr = row0 + tr + i;
            if (gr >= NN) continue;
            #pragma unroll
            for (int j = 0; j < 4; j++)
                g_root[(size_t)gr * 64 + tc + j] = acc[i][j];
        }
    }
}

// ---------------- K_edge: gather / weight / scatter --------------------------
__global__ __launch_bounds__(256) void k_edge(
    const void* __restrict__ eidx,
    const float* __restrict__ eattr,
    const float* __restrict__ mu,
    const float* __restrict__ sigma)
{
    const int lane  = threadIdx.x & 31;
    const int warp  = ((int)blockIdx.x * (int)blockDim.x + (int)threadIdx.x) >> 5;
    const int nwarp = ((int)gridDim.x * (int)blockDim.x) >> 5;
    const int is64  = g_is64;

    // lanes 0..7 hold per-kernel Gaussian params
    float m0 = 0.f, m1 = 0.f, m2 = 0.f, iv0 = 0.f, iv1 = 0.f, iv2 = 0.f;
    if (lane < KKER) {
        m0 = mu[lane * 3 + 0]; m1 = mu[lane * 3 + 1]; m2 = mu[lane * 3 + 2];
        float s0 = sigma[lane * 3 + 0], s1 = sigma[lane * 3 + 1], s2 = sigma[lane * 3 + 2];
        iv0 = -0.5f / (1e-15f + s0 * s0);
        iv1 = -0.5f / (1e-15f + s1 * s1);
        iv2 = -0.5f / (1e-15f + s2 * s2);
    }

    const long long* e64 = (const long long*)eidx;
    const int*       e32 = (const int*)eidx;

    for (int e = warp; e < EE; e += nwarp) {
        long long src, dst;
        if (is64) { src = e64[e]; dst = e64[EE + e]; }
        else      { src = e32[e]; dst = e32[EE + e]; }

        float a0 = eattr[(size_t)e * 3 + 0];
        float a1 = eattr[(size_t)e * 3 + 1];
        float a2 = eattr[(size_t)e * 3 + 2];

        float gk = 0.0f;
        if (lane < KKER) {
            float d0 = a0 - m0, d1 = a1 - m1, d2 = a2 - m2;
            gk = __expf(d0 * d0 * iv0 + d1 * d1 * iv1 + d2 * d2 * iv2);
        }

        // gather: 8 coalesced half2 loads (128B each) from L2-resident g_xt_h
        const __half2* xr = g_xt_h + (size_t)src * 256;
        __half2 v[8];
        #pragma unroll
        for (int k = 0; k < 8; k++) v[k] = xr[k * 32 + lane];

        float acc0 = 0.0f, acc1 = 0.0f;
        #pragma unroll
        for (int k = 0; k < 8; k++) {
            float g = __shfl_sync(0xffffffffu, gk, k);
            float2 f = __half22float2(v[k]);
            acc0 = fmaf(g, f.x, acc0);
            acc1 = fmaf(g, f.y, acc1);
        }

        atomicAdd(&g_agg[(size_t)dst * 64 + lane], acc0);
        atomicAdd(&g_agg[(size_t)dst * 64 + 32 + lane], acc1);
        if (lane == 0) atomicAdd(&g_cnt[dst], 1.0f);
    }
}

// ---------------- K_combine: pre-BN values + channel sums -------------------
__global__ __launch_bounds__(256) void k_combine(
    const float* __restrict__ bias, float* __restrict__ out)
{
    const int c = threadIdx.x & 63;
    const int w = threadIdx.x >> 6;   // 0..3
    const float b = bias[c];

    float s = 0.0f, ss = 0.0f;
    for (int n = blockIdx.x * 4 + w; n < NN; n += gridDim.x * 4) {
        float cnt = g_cnt[n];
        float inv = 1.0f / fmaxf(cnt, 1.0f);
        float v = g_agg[(size_t)n * 64 + c] * inv + g_root[(size_t)n * 64 + c] + b;
        out[(size_t)n * 64 + c] = v;
        s += v; ss += v * v;
    }

    __shared__ float shs[4][64];
    __shared__ float shq[4][64];
    shs[w][c] = s; shq[w][c] = ss;
    __syncthreads();
    if (threadIdx.x < 64) {
        float S  = shs[0][c] + shs[1][c] + shs[2][c] + shs[3][c];
        float SS = shq[0][c] + shq[1][c] + shq[2][c] + shq[3][c];
        atomicAdd(&g_sums[c], S);
        atomicAdd(&g_sums[64 + c], SS);
    }
}

// ---------------- K_norm: batchnorm + leaky relu -----------------------------
__global__ __launch_bounds__(256) void k_norm(
    const float* __restrict__ gamma, const float* __restrict__ beta,
    float* __restrict__ out)
{
    long i = (long)blockIdx.x * blockDim.x + threadIdx.x;
    if (i >= (long)NN * 64) return;
    int c = (int)(i & 63);
    const float invN = 1.0f / (float)NN;
    float mean = g_sums[c] * invN;
    float var  = g_sums[64 + c] * invN - mean * mean;
    float v = (out[i] - mean) * rsqrtf(var + 1e-5f) * gamma[c] + beta[c];
    out[i] = (v > 0.0f) ? v : 0.01f * v;
}

// ---------------- launcher ---------------------------------------------------
extern "C" void kernel_launch(void* const* d_in, const int* in_sizes, int n_in,
                              void* d_out, int out_size)
{
    const float* x      = (const float*)d_in[0];
    const void*  eidx   = d_in[1];
    const float* eattr  = (const float*)d_in[2];
    const float* Wg     = (const float*)d_in[3];
    const float* mu     = (const float*)d_in[4];
    const float* sigma  = (const float*)d_in[5];
    const float* Wr     = (const float*)d_in[6];
    const float* bias   = (const float*)d_in[7];
    const float* gamma  = (const float*)d_in[8];
    const float* beta   = (const float*)d_in[9];
    float* out = (float*)d_out;

    {
        long total = (long)NN * 64 + NN + 128;
        int blocks = (int)((total + 255) / 256);
        k_zero<<<blocks, 256>>>();
    }
    k_detect<<<1, 32>>>((const int*)eidx);
    {
        dim3 grid((NN + 63) / 64, 9);
        k_gemm<<<grid, 256>>>(x, Wg, Wr);
    }
    k_edge<<<2368, 256>>>(eidx, eattr, mu, sigma);
    k_combine<<<512, 256>>>(bias, out);
    {
        int blocks = (int)(((long)NN * 64 + 255) / 256);
        k_norm<<<blocks, 256>>>(gamma, beta, out);
    }
}

// round 4
// speedup vs baseline: 1.6678x; 1.3583x over previous
#include <cuda_runtime.h>
#include <cuda_fp16.h>
#include <math.h>

#define NN 50000
#define EE 800000
#define KKER 8

// ---------------- scratch (static device globals; no allocation) ------------
__device__ __half2 g_xt_h[(size_t)NN * 256];  // packed x@W_g: [N][K=8][32] half2 = 51.2 MB
__device__ float   g_root[(size_t)NN * 64];   // x @ W_root   12.8 MB
__device__ float   g_agg[(size_t)NN * 64];    // scatter target 12.8 MB
__device__ float   g_cnt[NN];
__device__ float   g_sums[128];               // [0:64) sum, [64:128) sumsq
__device__ int     g_is64;

// ---------------- K_detect: sniff edge_idx dtype (int64 vs int32) ----------
__global__ void k_detect(const int* __restrict__ eidx_raw) {
    __shared__ int sh[8];
    int acc = 0;
    for (int i = threadIdx.x; i < 2048; i += 256) acc |= eidx_raw[2 * i + 1];
    // warp reduce
    for (int o = 16; o > 0; o >>= 1) acc |= __shfl_xor_sync(0xffffffffu, acc, o);
    if ((threadIdx.x & 31) == 0) sh[threadIdx.x >> 5] = acc;
    __syncthreads();
    if (threadIdx.x == 0) {
        int a = 0;
        #pragma unroll
        for (int i = 0; i < 8; i++) a |= sh[i];
        g_is64 = (a == 0) ? 1 : 0;
    }
}

// ---------------- K_zero ----------------------------------------------------
__global__ void k_zero() {
    long i = (long)blockIdx.x * blockDim.x + threadIdx.x;
    const long nagg = (long)NN * 64;
    if (i < nagg) g_agg[i] = 0.0f;
    else if (i < nagg + NN) g_cnt[i - nagg] = 0.0f;
    else if (i < nagg + NN + 128) g_sums[i - nagg - NN] = 0.0f;
}

// ---------------- K_gemm (tensor core): C[N,576] = x[N,64] @ [W_g | W_root] -
// One block = 128 rows. A tile (128x64 fp16) loaded once; loop over the nine
// 64-col blocks (kblk 0..7 = GMM kernels -> packed half2; kblk 8 = root fp32).
// Warp layout: 8 warps; wm = warp&3 (32 rows each), wn = warp>>2 (two 16+16
// col windows arranged so that paired channels c and c+32 land in the SAME
// warp: ns 0,1 -> cols wn*16+ns*8, ns 2,3 -> +32).
#define AS_STRIDE 66
#define BS_STRIDE 66

__device__ __forceinline__ void mma16816(float d[4], const unsigned a[4],
                                         const unsigned b[2]) {
    asm volatile(
        "mma.sync.aligned.m16n8k16.row.col.f32.f16.f16.f32 "
        "{%0,%1,%2,%3}, {%4,%5,%6,%7}, {%8,%9}, {%0,%1,%2,%3};\n"
        : "+f"(d[0]), "+f"(d[1]), "+f"(d[2]), "+f"(d[3])
        : "r"(a[0]), "r"(a[1]), "r"(a[2]), "r"(a[3]),
          "r"(b[0]), "r"(b[1]));
}

__global__ __launch_bounds__(256) void k_gemm_tc(
    const float* __restrict__ x, const float* __restrict__ Wg,
    const float* __restrict__ Wr)
{
    __shared__ __half As[128 * AS_STRIDE];   // A row-major [row][k]
    __shared__ __half BsT[64 * BS_STRIDE];   // B transposed [n][k]

    const int row0 = blockIdx.x * 128;
    const int tid  = threadIdx.x;
    const int warp = tid >> 5;
    const int lane = tid & 31;
    const int g    = lane >> 2;        // group id 0..7
    const int t2   = (lane & 3) * 2;   // 0,2,4,6

    const int wm = warp & 3;           // row sub-tile (32 rows)
    const int wn = warp >> 2;          // col sub-window (0..1)

    // ---- load A once: x[row0..row0+128][0..64] -> fp16
    #pragma unroll
    for (int i = tid; i < 128 * 64; i += 256) {
        int r = i >> 6, c = i & 63;
        int gr = row0 + r;
        float v = (gr < NN) ? x[(size_t)gr * 64 + c] : 0.0f;
        As[r * AS_STRIDE + c] = __float2half_rn(v);
    }

    for (int kblk = 0; kblk < 9; kblk++) {
        // ---- load B^T tile: BsT[n][k] = W[k][kblk*64 + n]
        __syncthreads();
        #pragma unroll
        for (int i = tid; i < 64 * 64; i += 256) {
            int k = i >> 6, c = i & 63;
            float v = (kblk < 8) ? Wg[k * 512 + kblk * 64 + c]
                                 : Wr[k * 64 + c];
            BsT[c * BS_STRIDE + k] = __float2half_rn(v);
        }
        __syncthreads();

        float acc[2][4][4];
        #pragma unroll
        for (int ms = 0; ms < 2; ms++)
            #pragma unroll
            for (int ns = 0; ns < 4; ns++)
                #pragma unroll
                for (int j = 0; j < 4; j++) acc[ms][ns][j] = 0.0f;

        #pragma unroll
        for (int kk = 0; kk < 4; kk++) {
            const int k0 = kk * 16;
            unsigned a[2][4];
            #pragma unroll
            for (int ms = 0; ms < 2; ms++) {
                int ar = wm * 32 + ms * 16;
                a[ms][0] = *(const unsigned*)&As[(ar + g)     * AS_STRIDE + k0 + t2];
                a[ms][1] = *(const unsigned*)&As[(ar + g + 8) * AS_STRIDE + k0 + t2];
                a[ms][2] = *(const unsigned*)&As[(ar + g)     * AS_STRIDE + k0 + t2 + 8];
                a[ms][3] = *(const unsigned*)&As[(ar + g + 8) * AS_STRIDE + k0 + t2 + 8];
            }
            #pragma unroll
            for (int ns = 0; ns < 4; ns++) {
                int ncol = wn * 16 + (ns & 1) * 8 + (ns >> 1) * 32 + g;
                unsigned b[2];
                b[0] = *(const unsigned*)&BsT[ncol * BS_STRIDE + k0 + t2];
                b[1] = *(const unsigned*)&BsT[ncol * BS_STRIDE + k0 + t2 + 8];
                mma16816(acc[0][ns], a[0], b);
                mma16816(acc[1][ns], a[1], b);
            }
        }
        // note: ns index maps to col base: (ns&1)*8 + (ns>>1)*32 + wn*16
        // so (ns, ns|2) pairs give columns c and c+32 with identical low bits.

        // ---- store
        if (kblk < 8) {
            #pragma unroll
            for (int ms = 0; ms < 2; ms++)
                #pragma unroll
                for (int ns = 0; ns < 2; ns++)
                    #pragma unroll
                    for (int j = 0; j < 4; j++) {
                        int row = row0 + wm * 32 + ms * 16 + g + ((j >> 1) ? 8 : 0);
                        int c   = wn * 16 + ns * 8 + t2 + (j & 1);
                        if (row < NN) {
                            __half2 h = __floats2half2_rn(acc[ms][ns][j],
                                                          acc[ms][ns + 2][j]);
                            g_xt_h[(size_t)row * 256 + kblk * 32 + c] = h;
                        }
                    }
        } else {
            #pragma unroll
            for (int ms = 0; ms < 2; ms++)
                #pragma unroll
                for (int ns = 0; ns < 4; ns++)
                    #pragma unroll
                    for (int j = 0; j < 4; j++) {
                        int row = row0 + wm * 32 + ms * 16 + g + ((j >> 1) ? 8 : 0);
                        int c   = wn * 16 + (ns & 1) * 8 + (ns >> 1) * 32 + t2 + (j & 1);
                        if (row < NN) g_root[(size_t)row * 64 + c] = acc[ms][ns][j];
                    }
        }
    }
}

// ---------------- K_edge: gather / weight / scatter --------------------------
__global__ __launch_bounds__(256) void k_edge(
    const void* __restrict__ eidx,
    const float* __restrict__ eattr,
    const float* __restrict__ mu,
    const float* __restrict__ sigma)
{
    const int lane  = threadIdx.x & 31;
    const int warp  = ((int)blockIdx.x * (int)blockDim.x + (int)threadIdx.x) >> 5;
    const int nwarp = ((int)gridDim.x * (int)blockDim.x) >> 5;
    const int is64  = g_is64;

    // lanes 0..7 hold per-kernel Gaussian params
    float m0 = 0.f, m1 = 0.f, m2 = 0.f, iv0 = 0.f, iv1 = 0.f, iv2 = 0.f;
    if (lane < KKER) {
        m0 = mu[lane * 3 + 0]; m1 = mu[lane * 3 + 1]; m2 = mu[lane * 3 + 2];
        float s0 = sigma[lane * 3 + 0], s1 = sigma[lane * 3 + 1], s2 = sigma[lane * 3 + 2];
        iv0 = -0.5f / (1e-15f + s0 * s0);
        iv1 = -0.5f / (1e-15f + s1 * s1);
        iv2 = -0.5f / (1e-15f + s2 * s2);
    }

    const long long* e64 = (const long long*)eidx;
    const int*       e32 = (const int*)eidx;

    for (int e = warp; e < EE; e += nwarp) {
        long long src, dst;
        if (is64) { src = e64[e]; dst = e64[EE + e]; }
        else      { src = e32[e]; dst = e32[EE + e]; }

        float a0 = eattr[(size_t)e * 3 + 0];
        float a1 = eattr[(size_t)e * 3 + 1];
        float a2 = eattr[(size_t)e * 3 + 2];

        float gk = 0.0f;
        if (lane < KKER) {
            float d0 = a0 - m0, d1 = a1 - m1, d2 = a2 - m2;
            gk = __expf(d0 * d0 * iv0 + d1 * d1 * iv1 + d2 * d2 * iv2);
        }

        // gather: 8 coalesced half2 loads (128B each) from L2-resident g_xt_h
        const __half2* xr = g_xt_h + (size_t)src * 256;
        __half2 v[8];
        #pragma unroll
        for (int k = 0; k < 8; k++) v[k] = xr[k * 32 + lane];

        float acc0 = 0.0f, acc1 = 0.0f;
        #pragma unroll
        for (int k = 0; k < 8; k++) {
            float g = __shfl_sync(0xffffffffu, gk, k);
            float2 f = __half22float2(v[k]);
            acc0 = fmaf(g, f.x, acc0);
            acc1 = fmaf(g, f.y, acc1);
        }

        atomicAdd(&g_agg[(size_t)dst * 64 + lane], acc0);
        atomicAdd(&g_agg[(size_t)dst * 64 + 32 + lane], acc1);
        if (lane == 0) atomicAdd(&g_cnt[dst], 1.0f);
    }
}

// ---------------- K_combine: pre-BN values + channel sums -------------------
__global__ __launch_bounds__(256) void k_combine(
    const float* __restrict__ bias, float* __restrict__ out)
{
    const int c = threadIdx.x & 63;
    const int w = threadIdx.x >> 6;   // 0..3
    const float b = bias[c];

    float s = 0.0f, ss = 0.0f;
    for (int n = blockIdx.x * 4 + w; n < NN; n += gridDim.x * 4) {
        float cnt = g_cnt[n];
        float inv = 1.0f / fmaxf(cnt, 1.0f);
        float v = g_agg[(size_t)n * 64 + c] * inv + g_root[(size_t)n * 64 + c] + b;
        out[(size_t)n * 64 + c] = v;
        s += v; ss += v * v;
    }

    __shared__ float shs[4][64];
    __shared__ float shq[4][64];
    shs[w][c] = s; shq[w][c] = ss;
    __syncthreads();
    if (threadIdx.x < 64) {
        float S  = shs[0][c] + shs[1][c] + shs[2][c] + shs[3][c];
        float SS = shq[0][c] + shq[1][c] + shq[2][c] + shq[3][c];
        atomicAdd(&g_sums[c], S);
        atomicAdd(&g_sums[64 + c], SS);
    }
}

// ---------------- K_norm: batchnorm + leaky relu -----------------------------
__global__ __launch_bounds__(256) void k_norm(
    const float* __restrict__ gamma, const float* __restrict__ beta,
    float* __restrict__ out)
{
    long i = (long)blockIdx.x * blockDim.x + threadIdx.x;
    if (i >= (long)NN * 64) return;
    int c = (int)(i & 63);
    const float invN = 1.0f / (float)NN;
    float mean = g_sums[c] * invN;
    float var  = g_sums[64 + c] * invN - mean * mean;
    float v = (out[i] - mean) * rsqrtf(var + 1e-5f) * gamma[c] + beta[c];
    out[i] = (v > 0.0f) ? v : 0.01f * v;
}

// ---------------- launcher ---------------------------------------------------
extern "C" void kernel_launch(void* const* d_in, const int* in_sizes, int n_in,
                              void* d_out, int out_size)
{
    const float* x      = (const float*)d_in[0];
    const void*  eidx   = d_in[1];
    const float* eattr  = (const float*)d_in[2];
    const float* Wg     = (const float*)d_in[3];
    const float* mu     = (const float*)d_in[4];
    const float* sigma  = (const float*)d_in[5];
    const float* Wr     = (const float*)d_in[6];
    const float* bias   = (const float*)d_in[7];
    const float* gamma  = (const float*)d_in[8];
    const float* beta   = (const float*)d_in[9];
    float* out = (float*)d_out;

    {
        long total = (long)NN * 64 + NN + 128;
        int blocks = (int)((total + 255) / 256);
        k_zero<<<blocks, 256>>>();
    }
    k_detect<<<1, 256>>>((const int*)eidx);
    k_gemm_tc<<<(NN + 127) / 128, 256>>>(x, Wg, Wr);
    k_edge<<<2368, 256>>>(eidx, eattr, mu, sigma);
    k_combine<<<512, 256>>>(bias, out);
    {
        int blocks = (int)(((long)NN * 64 + 255) / 256);
        k_norm<<<blocks, 256>>>(gamma, beta, out);
    }
}

// round 5
// speedup vs baseline: 1.7966x; 1.0773x over previous
#include <cuda_runtime.h>
#include <cuda_fp16.h>
#include <math.h>

#define NN 50000
#define EE 800000
#define KKER 8

// ---------------- scratch (static device globals; no allocation) ------------
__device__ __half2 g_xt_h[(size_t)NN * 256];  // packed x@W_g: [N][K=8][32] half2 = 51.2 MB
__device__ float   g_root[(size_t)NN * 64];   // x @ W_root   12.8 MB
__device__ float   g_agg[(size_t)NN * 64];    // scatter target 12.8 MB
__device__ float   g_cnt[NN];
__device__ float   g_sums[128];               // [0:64) sum, [64:128) sumsq
__device__ int     g_is64;

// ---------------- K_detect: sniff edge_idx dtype (int64 vs int32) ----------
__global__ void k_detect(const int* __restrict__ eidx_raw) {
    __shared__ int sh[8];
    int acc = 0;
    for (int i = threadIdx.x; i < 2048; i += 256) acc |= eidx_raw[2 * i + 1];
    for (int o = 16; o > 0; o >>= 1) acc |= __shfl_xor_sync(0xffffffffu, acc, o);
    if ((threadIdx.x & 31) == 0) sh[threadIdx.x >> 5] = acc;
    __syncthreads();
    if (threadIdx.x == 0) {
        int a = 0;
        #pragma unroll
        for (int i = 0; i < 8; i++) a |= sh[i];
        g_is64 = (a == 0) ? 1 : 0;
    }
}

// ---------------- K_zero ----------------------------------------------------
__global__ void k_zero() {
    long i = (long)blockIdx.x * blockDim.x + threadIdx.x;
    const long nagg = (long)NN * 64;
    if (i < nagg) g_agg[i] = 0.0f;
    else if (i < nagg + NN) g_cnt[i - nagg] = 0.0f;
    else if (i < nagg + NN + 128) g_sums[i - nagg - NN] = 0.0f;
}

// ---------------- K_gemm (tensor core): C[N,576] = x[N,64] @ [W_g | W_root] -
#define AS_STRIDE 66
#define BS_STRIDE 66

__device__ __forceinline__ void mma16816(float d[4], const unsigned a[4],
                                         const unsigned b[2]) {
    asm volatile(
        "mma.sync.aligned.m16n8k16.row.col.f32.f16.f16.f32 "
        "{%0,%1,%2,%3}, {%4,%5,%6,%7}, {%8,%9}, {%0,%1,%2,%3};\n"
        : "+f"(d[0]), "+f"(d[1]), "+f"(d[2]), "+f"(d[3])
        : "r"(a[0]), "r"(a[1]), "r"(a[2]), "r"(a[3]),
          "r"(b[0]), "r"(b[1]));
}

__global__ __launch_bounds__(256) void k_gemm_tc(
    const float* __restrict__ x, const float* __restrict__ Wg,
    const float* __restrict__ Wr)
{
    __shared__ __half As[128 * AS_STRIDE];   // A row-major [row][k]
    __shared__ __half BsT[64 * BS_STRIDE];   // B transposed [n][k]

    const int row0 = blockIdx.x * 128;
    const int tid  = threadIdx.x;
    const int warp = tid >> 5;
    const int lane = tid & 31;
    const int g    = lane >> 2;        // group id 0..7
    const int t2   = (lane & 3) * 2;   // 0,2,4,6

    const int wm = warp & 3;           // row sub-tile (32 rows)
    const int wn = warp >> 2;          // col sub-window (0..1)

    // ---- load A once: x[row0..row0+128][0..64] -> fp16
    #pragma unroll
    for (int i = tid; i < 128 * 64; i += 256) {
        int r = i >> 6, c = i & 63;
        int gr = row0 + r;
        float v = (gr < NN) ? x[(size_t)gr * 64 + c] : 0.0f;
        As[r * AS_STRIDE + c] = __float2half_rn(v);
    }

    for (int kblk = 0; kblk < 9; kblk++) {
        __syncthreads();
        #pragma unroll
        for (int i = tid; i < 64 * 64; i += 256) {
            int k = i >> 6, c = i & 63;
            float v = (kblk < 8) ? Wg[k * 512 + kblk * 64 + c]
                                 : Wr[k * 64 + c];
            BsT[c * BS_STRIDE + k] = __float2half_rn(v);
        }
        __syncthreads();

        float acc[2][4][4];
        #pragma unroll
        for (int ms = 0; ms < 2; ms++)
            #pragma unroll
            for (int ns = 0; ns < 4; ns++)
                #pragma unroll
                for (int j = 0; j < 4; j++) acc[ms][ns][j] = 0.0f;

        #pragma unroll
        for (int kk = 0; kk < 4; kk++) {
            const int k0 = kk * 16;
            unsigned a[2][4];
            #pragma unroll
            for (int ms = 0; ms < 2; ms++) {
                int ar = wm * 32 + ms * 16;
                a[ms][0] = *(const unsigned*)&As[(ar + g)     * AS_STRIDE + k0 + t2];
                a[ms][1] = *(const unsigned*)&As[(ar + g + 8) * AS_STRIDE + k0 + t2];
                a[ms][2] = *(const unsigned*)&As[(ar + g)     * AS_STRIDE + k0 + t2 + 8];
                a[ms][3] = *(const unsigned*)&As[(ar + g + 8) * AS_STRIDE + k0 + t2 + 8];
            }
            #pragma unroll
            for (int ns = 0; ns < 4; ns++) {
                int ncol = wn * 16 + (ns & 1) * 8 + (ns >> 1) * 32 + g;
                unsigned b[2];
                b[0] = *(const unsigned*)&BsT[ncol * BS_STRIDE + k0 + t2];
                b[1] = *(const unsigned*)&BsT[ncol * BS_STRIDE + k0 + t2 + 8];
                mma16816(acc[0][ns], a[0], b);
                mma16816(acc[1][ns], a[1], b);
            }
        }

        if (kblk < 8) {
            #pragma unroll
            for (int ms = 0; ms < 2; ms++)
                #pragma unroll
                for (int ns = 0; ns < 2; ns++)
                    #pragma unroll
                    for (int j = 0; j < 4; j++) {
                        int row = row0 + wm * 32 + ms * 16 + g + ((j >> 1) ? 8 : 0);
                        int c   = wn * 16 + ns * 8 + t2 + (j & 1);
                        if (row < NN) {
                            __half2 h = __floats2half2_rn(acc[ms][ns][j],
                                                          acc[ms][ns + 2][j]);
                            g_xt_h[(size_t)row * 256 + kblk * 32 + c] = h;
                        }
                    }
        } else {
            #pragma unroll
            for (int ms = 0; ms < 2; ms++)
                #pragma unroll
                for (int ns = 0; ns < 4; ns++)
                    #pragma unroll
                    for (int j = 0; j < 4; j++) {
                        int row = row0 + wm * 32 + ms * 16 + g + ((j >> 1) ? 8 : 0);
                        int c   = wn * 16 + (ns & 1) * 8 + (ns >> 1) * 32 + t2 + (j & 1);
                        if (row < NN) g_root[(size_t)row * 64 + c] = acc[ms][ns][j];
                    }
        }
    }
}

// ---------------- K_edge: gather / weight / scatter (2-edge ILP) ------------
template <bool IS64>
__device__ __forceinline__ void edge_loop(
    const void* __restrict__ eidx,
    const float* __restrict__ eattr,
    float m0, float m1, float m2, float iv0, float iv1, float iv2,
    int lane, int warp, int nwarp)
{
    const long long* e64 = (const long long*)eidx;
    const int*       e32 = (const int*)eidx;

    // EE is even, stride is even -> e+1 always valid when e < EE.
    for (int e = warp * 2; e < EE; e += nwarp * 2) {
        long long srcA, dstA, srcB, dstB;
        if (IS64) {
            srcA = e64[e];     dstA = e64[EE + e];
            srcB = e64[e + 1]; dstB = e64[EE + e + 1];
        } else {
            srcA = e32[e];     dstA = e32[EE + e];
            srcB = e32[e + 1]; dstB = e32[EE + e + 1];
        }

        float aA0 = eattr[(size_t)e * 3 + 0];
        float aA1 = eattr[(size_t)e * 3 + 1];
        float aA2 = eattr[(size_t)e * 3 + 2];
        float aB0 = eattr[(size_t)e * 3 + 3];
        float aB1 = eattr[(size_t)e * 3 + 4];
        float aB2 = eattr[(size_t)e * 3 + 5];

        // issue both gathers up front for MLP
        const __half2* xrA = g_xt_h + (size_t)srcA * 256;
        const __half2* xrB = g_xt_h + (size_t)srcB * 256;
        __half2 vA[8], vB[8];
        #pragma unroll
        for (int k = 0; k < 8; k++) vA[k] = xrA[k * 32 + lane];
        #pragma unroll
        for (int k = 0; k < 8; k++) vB[k] = xrB[k * 32 + lane];

        float gkA = 0.0f, gkB = 0.0f;
        if (lane < KKER) {
            float d0 = aA0 - m0, d1 = aA1 - m1, d2 = aA2 - m2;
            gkA = __expf(d0 * d0 * iv0 + d1 * d1 * iv1 + d2 * d2 * iv2);
            d0 = aB0 - m0; d1 = aB1 - m1; d2 = aB2 - m2;
            gkB = __expf(d0 * d0 * iv0 + d1 * d1 * iv1 + d2 * d2 * iv2);
        }

        float accA0 = 0.0f, accA1 = 0.0f, accB0 = 0.0f, accB1 = 0.0f;
        #pragma unroll
        for (int k = 0; k < 8; k++) {
            float gA = __shfl_sync(0xffffffffu, gkA, k);
            float gB = __shfl_sync(0xffffffffu, gkB, k);
            float2 fA = __half22float2(vA[k]);
            float2 fB = __half22float2(vB[k]);
            accA0 = fmaf(gA, fA.x, accA0);
            accA1 = fmaf(gA, fA.y, accA1);
            accB0 = fmaf(gB, fB.x, accB0);
            accB1 = fmaf(gB, fB.y, accB1);
        }

        atomicAdd(&g_agg[(size_t)dstA * 64 + lane], accA0);
        atomicAdd(&g_agg[(size_t)dstA * 64 + 32 + lane], accA1);
        atomicAdd(&g_agg[(size_t)dstB * 64 + lane], accB0);
        atomicAdd(&g_agg[(size_t)dstB * 64 + 32 + lane], accB1);
        if (lane == 0) {
            atomicAdd(&g_cnt[dstA], 1.0f);
            atomicAdd(&g_cnt[dstB], 1.0f);
        }
    }
}

__global__ __launch_bounds__(256) void k_edge(
    const void* __restrict__ eidx,
    const float* __restrict__ eattr,
    const float* __restrict__ mu,
    const float* __restrict__ sigma)
{
    const int lane  = threadIdx.x & 31;
    const int warp  = ((int)blockIdx.x * (int)blockDim.x + (int)threadIdx.x) >> 5;
    const int nwarp = ((int)gridDim.x * (int)blockDim.x) >> 5;

    float m0 = 0.f, m1 = 0.f, m2 = 0.f, iv0 = 0.f, iv1 = 0.f, iv2 = 0.f;
    if (lane < KKER) {
        m0 = mu[lane * 3 + 0]; m1 = mu[lane * 3 + 1]; m2 = mu[lane * 3 + 2];
        float s0 = sigma[lane * 3 + 0], s1 = sigma[lane * 3 + 1], s2 = sigma[lane * 3 + 2];
        iv0 = -0.5f / (1e-15f + s0 * s0);
        iv1 = -0.5f / (1e-15f + s1 * s1);
        iv2 = -0.5f / (1e-15f + s2 * s2);
    }

    if (g_is64) edge_loop<true >(eidx, eattr, m0, m1, m2, iv0, iv1, iv2, lane, warp, nwarp);
    else        edge_loop<false>(eidx, eattr, m0, m1, m2, iv0, iv1, iv2, lane, warp, nwarp);
}

// ---------------- K_combine: pre-BN values + channel sums -------------------
__global__ __launch_bounds__(256) void k_combine(
    const float* __restrict__ bias, float* __restrict__ out)
{
    const int c = threadIdx.x & 63;
    const int w = threadIdx.x >> 6;   // 0..3
    const float b = bias[c];

    float s = 0.0f, ss = 0.0f;
    for (int n = blockIdx.x * 4 + w; n < NN; n += gridDim.x * 4) {
        float cnt = g_cnt[n];
        float inv = 1.0f / fmaxf(cnt, 1.0f);
        float v = g_agg[(size_t)n * 64 + c] * inv + g_root[(size_t)n * 64 + c] + b;
        out[(size_t)n * 64 + c] = v;
        s += v; ss += v * v;
    }

    __shared__ float shs[4][64];
    __shared__ float shq[4][64];
    shs[w][c] = s; shq[w][c] = ss;
    __syncthreads();
    if (threadIdx.x < 64) {
        float S  = shs[0][c] + shs[1][c] + shs[2][c] + shs[3][c];
        float SS = shq[0][c] + shq[1][c] + shq[2][c] + shq[3][c];
        atomicAdd(&g_sums[c], S);
        atomicAdd(&g_sums[64 + c], SS);
    }
}

// ---------------- K_norm: batchnorm + leaky relu -----------------------------
__global__ __launch_bounds__(256) void k_norm(
    const float* __restrict__ gamma, const float* __restrict__ beta,
    float* __restrict__ out)
{
    long i = (long)blockIdx.x * blockDim.x + threadIdx.x;
    if (i >= (long)NN * 64) return;
    int c = (int)(i & 63);
    const float invN = 1.0f / (float)NN;
    float mean = g_sums[c] * invN;
    float var  = g_sums[64 + c] * invN - mean * mean;
    float v = (out[i] - mean) * rsqrtf(var + 1e-5f) * gamma[c] + beta[c];
    out[i] = (v > 0.0f) ? v : 0.01f * v;
}

// ---------------- launcher ---------------------------------------------------
extern "C" void kernel_launch(void* const* d_in, const int* in_sizes, int n_in,
                              void* d_out, int out_size)
{
    const float* x      = (const float*)d_in[0];
    const void*  eidx   = d_in[1];
    const float* eattr  = (const float*)d_in[2];
    const float* Wg     = (const float*)d_in[3];
    const float* mu     = (const float*)d_in[4];
    const float* sigma  = (const float*)d_in[5];
    const float* Wr     = (const float*)d_in[6];
    const float* bias   = (const float*)d_in[7];
    const float* gamma  = (const float*)d_in[8];
    const float* beta   = (const float*)d_in[9];
    float* out = (float*)d_out;

    {
        long total = (long)NN * 64 + NN + 128;
        int blocks = (int)((total + 255) / 256);
        k_zero<<<blocks, 256>>>();
    }
    k_detect<<<1, 256>>>((const int*)eidx);
    k_gemm_tc<<<(NN + 127) / 128, 256>>>(x, Wg, Wr);
    k_edge<<<2368, 256>>>(eidx, eattr, mu, sigma);
    k_combine<<<512, 256>>>(bias, out);
    {
        int blocks = (int)(((long)NN * 64 + 255) / 256);
        k_norm<<<blocks, 256>>>(gamma, beta, out);
    }
}